// round 16
// baseline (speedup 1.0000x reference)
#include <cuda_runtime.h>
#include <cuda_bf16.h>
#include <cstdint>

// ---------------- problem constants ----------------
#define BB 8
#define TT 8
#define CC 128
#define NSP 1024
#define KK 512
#define DI 256
#define DS 16
#define DTR 8
#define NH 4
#define DH 32
#define ROWS 32768
#define NBATCH 256

// ---------------- device scratch ----------------
__device__ float    g_xm  [BB*CC*NSP];
__device__ float    g_h1  [BB*32*NSP];
__device__ int      g_idx [BB*KK];
__device__ float    g_scl [BB*KK];
__device__ uint32_t g_z0p [(size_t)ROWS*64];    // bf16x2 z0
__device__ uint32_t g_xzp [(size_t)ROWS*256];   // bf16x2 xz (x | z halves)
__device__ uint32_t g_xcp [(size_t)ROWS*128];   // bf16x2 xc
__device__ float    g_xdbl[(size_t)ROWS*40];
__device__ uint32_t g_ygp [(size_t)ROWS*128];   // bf16x2 yg
__device__ float    g_zs  [(size_t)ROWS*CC];    // fp32 (residual path)
__device__ uint32_t g_qkvp[(size_t)ROWS*192];   // bf16x2 qkv (Q pre-scaled)
__device__ uint32_t g_orpp[(size_t)ROWS*64];    // bf16x2 attn out

// ---------------- helpers ----------------
__device__ __forceinline__ float sigm(float x){ return 1.f/(1.f+__expf(-x)); }
__device__ __forceinline__ float siluf(float x){ return x*sigm(x); }
__device__ __forceinline__ float softplusf(float x){ return (x>20.f)?x:log1pf(__expf(x)); }

__device__ __forceinline__ uint32_t pk(float lo, float hi){
    __nv_bfloat162 v = __floats2bfloat162_rn(lo, hi);
    return *reinterpret_cast<uint32_t*>(&v);
}
__device__ __forceinline__ float2 unpk(uint32_t w){
    __nv_bfloat162 h = *reinterpret_cast<__nv_bfloat162*>(&w);
    return __bfloat1622float2(h);
}

__device__ __forceinline__ void mma_bf16(float* c, const uint32_t* a, const uint32_t* b){
    asm volatile(
        "mma.sync.aligned.m16n8k16.row.col.f32.bf16.bf16.f32 "
        "{%0,%1,%2,%3}, {%4,%5,%6,%7}, {%8,%9}, {%0,%1,%2,%3};"
        : "+f"(c[0]), "+f"(c[1]), "+f"(c[2]), "+f"(c[3])
        : "r"(a[0]), "r"(a[1]), "r"(a[2]), "r"(a[3]), "r"(b[0]), "r"(b[1]));
}

// ---------------- bf16 tensor-core TN GEMM ----------------
// A: fp32 (ABF=false) or packed bf16x2 (ABF=true, lda in words).
// MODE 0: fp32 out. MODE 1: fp32 out + (b,k,t)->(b,t,k) permute.
// MODE 2: bias + residual + LayerNorm + k-coalesced scatter-add into output.
// MODE 4: bf16x2 packed out, cols < CC scaled by 1/sqrt(dh).
// MODE 5: bf16x2 packed out, no scaling.
template<int BN, int MODE, bool ABF>
__global__ __launch_bounds__(256)
void gemm_bf(const void* __restrict__ Av, const float* __restrict__ Bw,
             const float* __restrict__ bias, void* __restrict__ Cv,
             int M, int N, int Kd, int lda, int ldb, int ldc,
             const float* __restrict__ zres, const float* __restrict__ lnw,
             const float* __restrict__ lnb, const int* __restrict__ idxp)
{
    constexpr int NF = BN/16;
    constexpr int BU = BN/32;
    __shared__ union SU {
        struct { uint32_t As[2][128][20]; uint32_t Bs[2][BN][20]; } g;
        struct { float red[128][17]; float tile[128][33]; int nsh[32]; } e;
    } S;

    const float* A = (const float*)Av;
    const uint32_t* A32 = (const uint32_t*)Av;
    float* C = (float*)Cv;
    uint32_t* C32 = (uint32_t*)Cv;

    int m0 = blockIdx.y*128, n0 = blockIdx.x*BN;
    int tid = threadIdx.x;
    int wid = tid >> 5, lane = tid & 31;
    int warp_m = wid >> 1, warp_n = wid & 1;
    int g = lane >> 2, t = lane & 3;

    float acc[2][NF][4] = {};
    float4 ra[4]; uint4 ua[2];
    float4 rb[BU];
    int nk = Kd >> 5;
    const float qscl = 0.17677669529663687f;

    if (ABF){
        #pragma unroll
        for (int u=0;u<2;u++){
            int f = tid + u*256; int w4 = f&3, m = f>>2;
            ua[u] = *(const uint4*)(A32 + (long)(m0+m)*lda + w4*4);
        }
    } else {
        #pragma unroll
        for (int u=0;u<4;u++){
            int f = tid + u*256; int k4 = f&7, m = f>>3;
            ra[u] = *(const float4*)(A + (long)(m0+m)*lda + k4*4);
        }
    }
    #pragma unroll
    for (int u=0;u<BU;u++){
        int f = tid + u*256; int k4 = f&7, n = f>>3;
        int gn = n0 + n;
        float4 v = {0.f,0.f,0.f,0.f};
        if (gn < N) v = *(const float4*)(Bw + (long)gn*ldb + k4*4);
        rb[u] = v;
    }
    if (ABF){
        #pragma unroll
        for (int u=0;u<2;u++){
            int f = tid + u*256; int w4 = f&3, m = f>>2;
            *(uint4*)&S.g.As[0][m][w4*4] = ua[u];
        }
    } else {
        #pragma unroll
        for (int u=0;u<4;u++){
            int f = tid + u*256; int k4 = f&7, m = f>>3;
            S.g.As[0][m][k4*2]   = pk(ra[u].x, ra[u].y);
            S.g.As[0][m][k4*2+1] = pk(ra[u].z, ra[u].w);
        }
    }
    #pragma unroll
    for (int u=0;u<BU;u++){
        int f = tid + u*256; int k4 = f&7, n = f>>3;
        S.g.Bs[0][n][k4*2]   = pk(rb[u].x, rb[u].y);
        S.g.Bs[0][n][k4*2+1] = pk(rb[u].z, rb[u].w);
    }
    __syncthreads();

    int buf = 0;
    for (int kt = 0; kt < nk; kt++){
        if (kt+1 < nk){
            if (ABF){
                int kw0 = (kt+1)*16;
                #pragma unroll
                for (int u=0;u<2;u++){
                    int f = tid + u*256; int w4 = f&3, m = f>>2;
                    ua[u] = *(const uint4*)(A32 + (long)(m0+m)*lda + kw0 + w4*4);
                }
            } else {
                int k0 = (kt+1)*32;
                #pragma unroll
                for (int u=0;u<4;u++){
                    int f = tid + u*256; int k4 = f&7, m = f>>3;
                    ra[u] = *(const float4*)(A + (long)(m0+m)*lda + k0 + k4*4);
                }
            }
            int k0 = (kt+1)*32;
            #pragma unroll
            for (int u=0;u<BU;u++){
                int f = tid + u*256; int k4 = f&7, n = f>>3;
                int gn = n0 + n;
                float4 v = {0.f,0.f,0.f,0.f};
                if (gn < N) v = *(const float4*)(Bw + (long)gn*ldb + k0 + k4*4);
                rb[u] = v;
            }
        }
        #pragma unroll
        for (int ks=0; ks<2; ks++){
            int kc2 = ks*8;
            uint32_t af[2][4], bfr[NF][2];
            #pragma unroll
            for (int mf=0; mf<2; mf++){
                int r = warp_m*32 + mf*16 + g;
                af[mf][0] = S.g.As[buf][r][kc2+t];
                af[mf][1] = S.g.As[buf][r+8][kc2+t];
                af[mf][2] = S.g.As[buf][r][kc2+t+4];
                af[mf][3] = S.g.As[buf][r+8][kc2+t+4];
            }
            #pragma unroll
            for (int nf=0; nf<NF; nf++){
                int cn = warp_n*(BN/2) + nf*8 + g;
                bfr[nf][0] = S.g.Bs[buf][cn][kc2+t];
                bfr[nf][1] = S.g.Bs[buf][cn][kc2+t+4];
            }
            #pragma unroll
            for (int mf=0; mf<2; mf++)
                #pragma unroll
                for (int nf=0; nf<NF; nf++)
                    mma_bf16(acc[mf][nf], af[mf], bfr[nf]);
        }
        if (kt+1 < nk){
            int nb = buf^1;
            if (ABF){
                #pragma unroll
                for (int u=0;u<2;u++){
                    int f = tid + u*256; int w4 = f&3, m = f>>2;
                    *(uint4*)&S.g.As[nb][m][w4*4] = ua[u];
                }
            } else {
                #pragma unroll
                for (int u=0;u<4;u++){
                    int f = tid + u*256; int k4 = f&7, m = f>>3;
                    S.g.As[nb][m][k4*2]   = pk(ra[u].x, ra[u].y);
                    S.g.As[nb][m][k4*2+1] = pk(ra[u].z, ra[u].w);
                }
            }
            #pragma unroll
            for (int u=0;u<BU;u++){
                int f = tid + u*256; int k4 = f&7, n = f>>3;
                S.g.Bs[nb][n][k4*2]   = pk(rb[u].x, rb[u].y);
                S.g.Bs[nb][n][k4*2+1] = pk(rb[u].z, rb[u].w);
            }
            __syncthreads();
            buf = nb;
        }
    }

    if (MODE == 2){
        __syncthreads();
        float sum[2][2] = {}, sq[2][2] = {};
        #pragma unroll
        for (int mf=0;mf<2;mf++){
            int rl0 = warp_m*32 + mf*16 + g;
            long gr0 = m0 + rl0, gr1 = gr0 + 8;
            #pragma unroll
            for (int nf=0;nf<NF;nf++){
                int cn = warp_n*(BN/2) + nf*8 + 2*t;
                float b0 = bias[cn], b1 = bias[cn+1];
                float v0 = acc[mf][nf][0] + b0 + zres[gr0*CC + cn];
                float v1 = acc[mf][nf][1] + b1 + zres[gr0*CC + cn+1];
                float v2 = acc[mf][nf][2] + b0 + zres[gr1*CC + cn];
                float v3 = acc[mf][nf][3] + b1 + zres[gr1*CC + cn+1];
                acc[mf][nf][0]=v0; acc[mf][nf][1]=v1; acc[mf][nf][2]=v2; acc[mf][nf][3]=v3;
                sum[mf][0] += v0+v1;   sum[mf][1] += v2+v3;
                sq[mf][0]  += v0*v0+v1*v1; sq[mf][1] += v2*v2+v3*v3;
            }
        }
        int cid = warp_n*4 + t;
        #pragma unroll
        for (int mf=0;mf<2;mf++){
            int rl0 = warp_m*32 + mf*16 + g;
            S.e.red[rl0][cid]     = sum[mf][0];  S.e.red[rl0][8+cid]   = sq[mf][0];
            S.e.red[rl0+8][cid]   = sum[mf][1];  S.e.red[rl0+8][8+cid] = sq[mf][1];
        }
        __syncthreads();
        float mu_[2][2], rs_[2][2];
        #pragma unroll
        for (int mf=0;mf<2;mf++)
            #pragma unroll
            for (int half=0; half<2; half++){
                int rl = warp_m*32 + mf*16 + g + half*8;
                float s8 = 0.f, q8 = 0.f;
                #pragma unroll
                for (int j=0;j<8;j++){ s8 += S.e.red[rl][j]; q8 += S.e.red[rl][8+j]; }
                float mu = s8 * (1.f/128.f);
                float var = q8 * (1.f/128.f) - mu*mu;
                mu_[mf][half] = mu;
                rs_[mf][half] = rsqrtf(var + 1e-5f);
            }
        long bt = m0 >> 9;
        int bidx = (int)(bt >> 3);
        int kbase = m0 & 511;
        float* Cb0 = C + (bt*CC)*NSP;
        #pragma unroll
        for (int chunk=0; chunk<4; chunk++){
            __syncthreads();
            if (tid < 32) S.e.nsh[tid] = idxp[bidx*KK + kbase + chunk*32 + tid];
            if (warp_m == chunk){
                #pragma unroll
                for (int mf=0; mf<2; mf++)
                    #pragma unroll
                    for (int half=0; half<2; half++){
                        int kl = mf*16 + g + half*8;
                        float mu = mu_[mf][half], rs = rs_[mf][half];
                        #pragma unroll
                        for (int nf=0; nf<NF; nf++){
                            int cn = warp_n*(BN/2) + nf*8 + 2*t;
                            S.e.tile[cn][kl]   = (acc[mf][nf][half*2]   - mu)*rs*lnw[cn]   + lnb[cn];
                            S.e.tile[cn+1][kl] = (acc[mf][nf][half*2+1] - mu)*rs*lnw[cn+1] + lnb[cn+1];
                        }
                    }
            }
            __syncthreads();
            #pragma unroll
            for (int u=0; u<16; u++){
                int e = tid + u*256;
                int k = e & 31, c = e >> 5;
                Cb0[(long)c*NSP + S.e.nsh[k]] += S.e.tile[c][k];
            }
        }
        return;
    }

    #pragma unroll
    for (int mf=0; mf<2; mf++){
        int r0 = m0 + warp_m*32 + mf*16 + g;
        int r1 = r0 + 8;
        long gr0 = r0, gr1 = r1;
        if (MODE==1){
            int b = r0 >> 12; int k = (r0 >> 3) & 511; int tt = r0 & 7;
            gr0 = ((long)(b*8 + tt) << 9) + k;
            b = r1 >> 12; k = (r1 >> 3) & 511; tt = r1 & 7;
            gr1 = ((long)(b*8 + tt) << 9) + k;
        }
        #pragma unroll
        for (int nf=0; nf<NF; nf++){
            int cn = n0 + warp_n*(BN/2) + nf*8 + 2*t;
            if (cn >= N) continue;
            float b0 = bias ? bias[cn]   : 0.f;
            float b1 = bias ? bias[cn+1] : 0.f;
            float v0 = acc[mf][nf][0] + b0;
            float v1 = acc[mf][nf][1] + b1;
            float v2 = acc[mf][nf][2] + b0;
            float v3 = acc[mf][nf][3] + b1;
            if (MODE==4 || MODE==5){
                if (MODE==4 && cn < CC){ v0*=qscl; v1*=qscl; v2*=qscl; v3*=qscl; }
                C32[gr0*ldc + (cn>>1)] = pk(v0, v1);
                C32[gr1*ldc + (cn>>1)] = pk(v2, v3);
            } else {
                C[gr0*ldc + cn]   = v0;
                C[gr0*ldc + cn+1] = v1;
                C[gr1*ldc + cn]   = v2;
                C[gr1*ldc + cn+1] = v3;
            }
        }
    }
}

// ---------------- bf16 flash attention, q-tile 128, packed qkv ----------------
__global__ __launch_bounds__(256)
void k_flash2(const uint32_t* __restrict__ qkvp, uint32_t* __restrict__ op)
{
    extern __shared__ char smraw[];
    uint32_t (*Qs)[20] = (uint32_t(*)[20])(smraw);
    uint32_t (*Ks)[20] = (uint32_t(*)[20])(smraw + 10240);
    uint32_t (*Vt)[36] = (uint32_t(*)[36])(smraw + 15360);
    uint32_t (*Ps)[68] = (uint32_t(*)[68])(smraw + 19968);
    float* m_s = (float*)(smraw + 54784);
    float* l_s = (float*)(smraw + 55296);
    float* r_s = (float*)(smraw + 55808);

    int bh = blockIdx.y;
    int bt = bh >> 2, h = bh & 3;
    const uint32_t* base = qkvp + (long)bt*KK*192 + h*16;
    int q0 = blockIdx.x * 128;

    int tid = threadIdx.x;
    int wid = tid >> 5, lane = tid & 31;
    int g = lane >> 2, t = lane & 3;

    for (int i = tid; i < 128*16; i += 256){
        int k2 = i & 15, q = i >> 4;
        Qs[q][k2] = base[(long)(q0+q)*192 + k2];
    }
    if (tid < 128){ m_s[tid] = -1e30f; l_s[tid] = 0.f; }

    int wm = wid & 3, wn = wid >> 2;
    int pm = wid;

    float oacc[4][4] = {};
    int qrow = tid >> 1, tr = tid & 1;

    for (int kc = 0; kc < 8; kc++){
        int k0 = kc * 64;
        __syncthreads();
        for (int i = tid; i < 64*16; i += 256){
            int k2 = i & 15, k = i >> 4;
            Ks[k][k2] = base[(long)(k0+k)*192 + 64 + k2];
        }
        for (int i = tid; i < 16*32; i += 256){
            int d2 = i & 15, j = i >> 4;
            uint32_t w0 = base[(long)(k0+2*j)  *192 + 128 + d2];
            uint32_t w1 = base[(long)(k0+2*j+1)*192 + 128 + d2];
            Vt[2*d2][j]   = __byte_perm(w0, w1, 0x5410);
            Vt[2*d2+1][j] = __byte_perm(w0, w1, 0x7632);
        }
        __syncthreads();

        float sacc[2][4][4] = {};
        #pragma unroll
        for (int ks=0; ks<2; ks++){
            int kc2 = ks*8;
            uint32_t af[2][4], bf[4][2];
            #pragma unroll
            for (int mf=0; mf<2; mf++){
                int r = wm*32 + mf*16 + g;
                af[mf][0] = Qs[r][kc2+t];
                af[mf][1] = Qs[r+8][kc2+t];
                af[mf][2] = Qs[r][kc2+t+4];
                af[mf][3] = Qs[r+8][kc2+t+4];
            }
            #pragma unroll
            for (int nf=0; nf<4; nf++){
                int cn = wn*32 + nf*8 + g;
                bf[nf][0] = Ks[cn][kc2+t];
                bf[nf][1] = Ks[cn][kc2+t+4];
            }
            #pragma unroll
            for (int mf=0; mf<2; mf++)
                #pragma unroll
                for (int nf=0; nf<4; nf++)
                    mma_bf16(sacc[mf][nf], af[mf], bf[nf]);
        }
        #pragma unroll
        for (int mf=0; mf<2; mf++){
            int r0 = wm*32 + mf*16 + g;
            #pragma unroll
            for (int nf=0; nf<4; nf++){
                int cn = wn*32 + nf*8 + 2*t;
                Ps[r0][cn]     = __float_as_uint(sacc[mf][nf][0]);
                Ps[r0][cn+1]   = __float_as_uint(sacc[mf][nf][1]);
                Ps[r0+8][cn]   = __float_as_uint(sacc[mf][nf][2]);
                Ps[r0+8][cn+1] = __float_as_uint(sacc[mf][nf][3]);
            }
        }
        __syncthreads();

        {
            float v[32]; float mx = -1e30f;
            #pragma unroll
            for (int j=0;j<32;j++){
                v[j] = __uint_as_float(Ps[qrow][tr*32 + j]);
                mx = fmaxf(mx, v[j]);
            }
            mx = fmaxf(mx, __shfl_xor_sync(0xffffffffu, mx, 1));
            float mold = m_s[qrow];
            float mnew = fmaxf(mold, mx);
            float sum = 0.f;
            #pragma unroll
            for (int j=0;j<32;j++){
                v[j] = __expf(v[j] - mnew);
                sum += v[j];
            }
            sum += __shfl_xor_sync(0xffffffffu, sum, 1);
            __syncwarp();
            #pragma unroll
            for (int j=0;j<16;j++)
                Ps[qrow][tr*16 + j] = pk(v[2*j], v[2*j+1]);
            if (tr == 0){
                float r = __expf(mold - mnew);
                l_s[qrow] = l_s[qrow]*r + sum;
                m_s[qrow] = mnew;
                r_s[qrow] = r;
            }
        }
        __syncthreads();

        {
            float rr0 = r_s[pm*16 + g];
            float rr1 = r_s[pm*16 + g + 8];
            #pragma unroll
            for (int nf=0; nf<4; nf++){
                oacc[nf][0] *= rr0; oacc[nf][1] *= rr0;
                oacc[nf][2] *= rr1; oacc[nf][3] *= rr1;
            }
            #pragma unroll
            for (int ks=0; ks<4; ks++){
                int kc2 = ks*8;
                uint32_t af[4], bf[4][2];
                int r = pm*16 + g;
                af[0] = Ps[r][kc2+t];
                af[1] = Ps[r+8][kc2+t];
                af[2] = Ps[r][kc2+t+4];
                af[3] = Ps[r+8][kc2+t+4];
                #pragma unroll
                for (int nf=0; nf<4; nf++){
                    int cn = nf*8 + g;
                    bf[nf][0] = Vt[cn][kc2+t];
                    bf[nf][1] = Vt[cn][kc2+t+4];
                }
                #pragma unroll
                for (int nf=0; nf<4; nf++)
                    mma_bf16(oacc[nf], af, bf[nf]);
            }
        }
    }
    __syncthreads();
    {
        float inv0 = 1.f / l_s[pm*16 + g];
        float inv1 = 1.f / l_s[pm*16 + g + 8];
        int qA = q0 + pm*16 + g;
        int qB = qA + 8;
        #pragma unroll
        for (int nf=0; nf<4; nf++){
            int d = nf*8 + 2*t;
            int w = (h*DH + d) >> 1;
            long rowA = ((long)bt*KK + qA)*64 + w;
            long rowB = ((long)bt*KK + qB)*64 + w;
            op[rowA] = pk(oacc[nf][0]*inv0, oacc[nf][1]*inv0);
            op[rowB] = pk(oacc[nf][2]*inv1, oacc[nf][3]*inv1);
        }
    }
}

// ---------------- stage kernels ----------------
__global__ void k_copy(const float4* __restrict__ in, float4* __restrict__ out, int n4){
    int i = blockIdx.x*blockDim.x + threadIdx.x;
    if (i < n4) out[i] = in[i];
}

__global__ void k_mean(const float* __restrict__ x, float* __restrict__ xm){
    int i = blockIdx.x*blockDim.x + threadIdx.x;
    if (i >= BB*CC*NSP) return;
    int b = i >> 17; int rem = i & 131071;
    float s = 0.f;
    #pragma unroll
    for (int t=0;t<TT;t++) s += x[((long)b*TT+t)*131072 + rem];
    xm[i] = s * 0.125f;
}

// router conv 3x3: 4 input channels per staging round (64 barriers vs 256)
__global__ void k_conv3(const float* __restrict__ xm, const float* __restrict__ w,
                        const float* __restrict__ bias, float* __restrict__ h1){
    __shared__ float pl[4][34*34];
    int bo = blockIdx.x; int b = bo >> 5; int oc = bo & 31;
    int tid = threadIdx.x;
    int h = tid >> 5, wq = tid & 31;
    float acc = 0.f;
    for (int ic0=0; ic0<CC; ic0+=4){
        __syncthreads();
        for (int i=tid; i<4*1156; i+=1024){
            int ic = i / 1156, r = i % 1156;
            int hh = r/34 - 1, ww = r%34 - 1;
            pl[ic][r] = (hh>=0 && hh<32 && ww>=0 && ww<32) ?
                        xm[((long)b*CC + ic0 + ic)*NSP + hh*32+ww] : 0.f;
        }
        __syncthreads();
        #pragma unroll
        for (int ic=0; ic<4; ic++){
            const float* wp = w + ((long)oc*CC + ic0 + ic)*9;
            #pragma unroll
            for (int kh=0;kh<3;kh++)
                #pragma unroll
                for (int kw=0;kw<3;kw++)
                    acc += pl[ic][(h+kh)*34 + (wq+kw)] * wp[kh*3+kw];
        }
    }
    acc += bias[oc];
    h1[(long)bo*NSP + tid] = (acc >= 0.f) ? acc : 0.01f*acc;
}

__global__ void k_scoretopk(const float* __restrict__ h1, const float* __restrict__ w2,
                            const float* __restrict__ b2, int* __restrict__ idx,
                            float* __restrict__ scl){
    __shared__ float s[1024];
    __shared__ unsigned char keep[1024];
    int b = blockIdx.x, n = threadIdx.x;
    float a = 0.f;
    #pragma unroll
    for (int oc=0;oc<32;oc++) a += h1[((long)b*32+oc)*NSP + n] * w2[oc];
    float v = sigm(a + b2[0]);
    s[n] = v;
    __syncthreads();
    int cnt = 0;
    for (int m=0;m<1024;m++){ float u = s[m]; cnt += (u>v) || (u==v && m<n); }
    keep[n] = (cnt < KK) ? 1 : 0;
    __syncthreads();
    if (keep[n]){
        int pos = 0;
        for (int m=0;m<n;m++) pos += keep[m];
        idx[b*KK + pos] = n;
        scl[b*KK + pos] = v / (v + 1e-6f);
    }
}

__global__ __launch_bounds__(256)
void k_gather2(const float* __restrict__ x, const int* __restrict__ idx,
               const float* __restrict__ scl, const float* __restrict__ nw,
               uint32_t* __restrict__ z0p){
    __shared__ float tile[128][33];
    __shared__ float red[32][9];
    __shared__ int   nsh[32];
    __shared__ float ssh[32];
    __shared__ float rst[32];
    int bt = blockIdx.x;
    int b = bt >> 3, t = bt & 7;
    int kc = blockIdx.y;
    int tid = threadIdx.x;
    if (tid < 32){
        nsh[tid] = idx[b*KK + kc*32 + tid];
        ssh[tid] = scl[b*KK + kc*32 + tid];
    }
    __syncthreads();
    const float* xb = x + ((long)bt*CC)*NSP;
    #pragma unroll
    for (int u=0; u<16; u++){
        int e = tid + u*256;
        int k = e & 31, c = e >> 5;
        tile[c][k] = xb[(long)c*NSP + nsh[k]] * ssh[k];
    }
    __syncthreads();
    {
        int k = tid & 31, part = tid >> 5;
        float s = 0.f;
        #pragma unroll
        for (int j=0;j<16;j++){ float v = tile[part*16+j][k]; s += v*v; }
        red[k][part] = s;
    }
    __syncthreads();
    if (tid < 32){
        float s = 0.f;
        #pragma unroll
        for (int p=0;p<8;p++) s += red[tid][p];
        rst[tid] = rsqrtf(s*(1.f/128.f) + 1e-5f);
    }
    __syncthreads();
    #pragma unroll
    for (int u=0; u<8; u++){
        int e = tid + u*256;
        int c2 = e & 63, k = e >> 6;
        long row = (((long)b*KK + kc*32 + k)*TT + t);
        float r = rst[k];
        z0p[row*64 + c2] = pk(tile[2*c2][k]*r*nw[2*c2], tile[2*c2+1][k]*r*nw[2*c2+1]);
    }
}

// conv1d + silu from packed xz, packed bf16 out
__global__ void k_conv1d(const uint32_t* __restrict__ xzp, const float* __restrict__ w,
                         const float* __restrict__ bias, uint32_t* __restrict__ xcp){
    int s = blockIdx.x; int c2 = threadIdx.x;   // 4096 blocks x 128 thr
    float2 in[TT];
    #pragma unroll
    for (int t=0;t<TT;t++)
        in[t] = unpk(xzp[((long)s*TT + t)*256 + c2]);
    int ch0 = 2*c2, ch1 = 2*c2+1;
    float a0_[4] = {w[ch0*4+0], w[ch0*4+1], w[ch0*4+2], w[ch0*4+3]};
    float a1_[4] = {w[ch1*4+0], w[ch1*4+1], w[ch1*4+2], w[ch1*4+3]};
    float b0 = bias[ch0], b1 = bias[ch1];
    #pragma unroll
    for (int t=0;t<TT;t++){
        float v0 = b0 + in[t].x*a0_[3];
        float v1 = b1 + in[t].y*a1_[3];
        if (t>=1){ v0 += in[t-1].x*a0_[2]; v1 += in[t-1].y*a1_[2]; }
        if (t>=2){ v0 += in[t-2].x*a0_[1]; v1 += in[t-2].y*a1_[1]; }
        if (t>=3){ v0 += in[t-3].x*a0_[0]; v1 += in[t-3].y*a1_[0]; }
        xcp[((long)s*TT + t)*128 + c2] = pk(siluf(v0), siluf(v1));
    }
}

// fused conv-recompute + dt_proj + scan + gate from packed xz, packed bf16 out
__global__ void k_scan3(const uint32_t* __restrict__ xzp, const float* __restrict__ xdbl,
                        const float* __restrict__ dtw, const float* __restrict__ dtbias,
                        const float* __restrict__ Alog, const float* __restrict__ Dp,
                        const float* __restrict__ cw, const float* __restrict__ cb,
                        uint32_t* __restrict__ ygp){
    __shared__ float xd[TT][40];
    __shared__ float ys[TT][256];
    int s = blockIdx.x; int ch = threadIdx.x;
    for (int i = ch; i < TT*40; i += 256)
        xd[i/40][i%40] = xdbl[(long)s*TT*40 + i];
    float w8[DTR];
    #pragma unroll
    for (int r=0;r<DTR;r++) w8[r] = dtw[ch*DTR + r];
    float db = dtbias[ch];
    float cw0=cw[ch*4+0], cw1=cw[ch*4+1], cw2=cw[ch*4+2], cw3=cw[ch*4+3];
    float cbb = cb[ch];
    int half = ch & 1;
    float in[TT], zg[TT];
    #pragma unroll
    for (int t=0;t<TT;t++){
        long rw = ((long)s*TT + t)*256;
        float2 vi = unpk(xzp[rw + (ch>>1)]);
        float2 vz = unpk(xzp[rw + 128 + (ch>>1)]);
        in[t] = half ? vi.y : vi.x;
        zg[t] = half ? vz.y : vz.x;
    }
    float Arow[DS];
    #pragma unroll
    for (int d=0;d<DS;d++) Arow[d] = -__expf(Alog[ch*DS + d]);
    float A0 = Arow[0];
    bool geom = true;
    #pragma unroll
    for (int d=1;d<DS;d++)
        geom = geom && (fabsf(Arow[d] - A0*(float)(d+1)) <= 1e-5f*fabsf(A0*(float)(d+1)) + 1e-12f);
    float Dv = Dp[ch];
    __syncthreads();
    float h[DS];
    #pragma unroll
    for (int d=0;d<DS;d++) h[d] = 0.f;
    #pragma unroll
    for (int t=0;t<TT;t++){
        float a = cbb + in[t]*cw3;
        if (t>=1) a += in[t-1]*cw2;
        if (t>=2) a += in[t-2]*cw1;
        if (t>=3) a += in[t-3]*cw0;
        float u = siluf(a);
        float dtr = db;
        #pragma unroll
        for (int r=0;r<DTR;r++) dtr += xd[t][r]*w8[r];
        float dt = softplusf(dtr);
        float du = dt*u;
        float y = 0.f;
        if (geom){
            float e1 = __expf(dt*A0);
            float ed = 1.f;
            #pragma unroll
            for (int d=0;d<DS;d++){
                ed *= e1;
                float Bv = xd[t][DTR + d];
                float Cv = xd[t][DTR + DS + d];
                h[d] = h[d]*ed + du*Bv;
                y += h[d]*Cv;
            }
        } else {
            #pragma unroll
            for (int d=0;d<DS;d++){
                float Bv = xd[t][DTR + d];
                float Cv = xd[t][DTR + DS + d];
                h[d] = h[d]*__expf(dt*Arow[d]) + du*Bv;
                y += h[d]*Cv;
            }
        }
        ys[t][ch] = (y + u*Dv) * siluf(zg[t]);
    }
    __syncthreads();
    for (int i = ch; i < TT*128; i += 256){
        int t = i >> 7, c2 = i & 127;
        ygp[((long)s*TT + t)*128 + c2] = pk(ys[t][2*c2], ys[t][2*c2+1]);
    }
}

// ---------------- host launch ----------------
static void* symv(const void* s){ void* p = nullptr; cudaGetSymbolAddress(&p, s); return p; }

extern "C" void kernel_launch(void* const* d_in, const int* in_sizes, int n_in,
                              void* d_out, int out_size)
{
    const float* x_in      = (const float*)d_in[0];
    const float* norm1_w   = (const float*)d_in[1];
    const float* in_proj_w = (const float*)d_in[2];
    const float* conv1d_w  = (const float*)d_in[3];
    const float* conv1d_b  = (const float*)d_in[4];
    const float* x_proj_w  = (const float*)d_in[5];
    const float* dt_proj_w = (const float*)d_in[6];
    const float* dt_proj_b = (const float*)d_in[7];
    const float* A_log     = (const float*)d_in[8];
    const float* Dp        = (const float*)d_in[9];
    const float* out_proj_w= (const float*)d_in[10];
    const float* r1_w      = (const float*)d_in[11];
    const float* r1_b      = (const float*)d_in[12];
    const float* r2_w      = (const float*)d_in[13];
    const float* r2_b      = (const float*)d_in[14];
    const float* attn_in_w = (const float*)d_in[15];
    const float* attn_in_b = (const float*)d_in[16];
    const float* attn_out_w= (const float*)d_in[17];
    const float* attn_out_b= (const float*)d_in[18];
    const float* ln_w      = (const float*)d_in[19];
    const float* ln_b      = (const float*)d_in[20];
    float* out = (float*)d_out;

    float *xm = (float*)symv(g_xm), *h1 = (float*)symv(g_h1);
    float *scl = (float*)symv(g_scl);
    float *xdbl = (float*)symv(g_xdbl), *zsb = (float*)symv(g_zs);
    uint32_t *z0p = (uint32_t*)symv(g_z0p), *xzp = (uint32_t*)symv(g_xzp);
    uint32_t *xcp = (uint32_t*)symv(g_xcp), *ygp = (uint32_t*)symv(g_ygp);
    uint32_t *qkvp = (uint32_t*)symv(g_qkvp), *orpp = (uint32_t*)symv(g_orpp);
    int* idx = (int*)symv(g_idx);

    static int smem_set = 0;
    if (!smem_set){
        cudaFuncSetAttribute(k_flash2, cudaFuncAttributeMaxDynamicSharedMemorySize, 57344);
        smem_set = 1;
    }

    // 1) router
    k_mean<<<(BB*CC*NSP+255)/256, 256>>>(x_in, xm);
    k_conv3<<<BB*32, 1024>>>(xm, r1_w, r1_b, h1);
    k_scoretopk<<<BB, 1024>>>(h1, r2_w, r2_b, idx, scl);
    // 2) gather + rmsnorm (bf16 out)   (profiled launch slot)
    k_gather2<<<dim3(BB*TT, 16), 256>>>(x_in, idx, scl, norm1_w, z0p);
    // 3) mamba (xz packed bf16)
    gemm_bf<128,5,true><<<dim3(4,256),256>>>(z0p, in_proj_w, nullptr, xzp,
        ROWS, 2*DI, CC, 64, CC, 256, nullptr, nullptr, nullptr, nullptr);
    k_conv1d<<<ROWS/TT, 128>>>(xzp, conv1d_w, conv1d_b, xcp);
    gemm_bf<64,0,true><<<dim3(1,256),256>>>(xcp, x_proj_w, nullptr, xdbl,
        ROWS, 40, DI, 128, DI, 40, nullptr, nullptr, nullptr, nullptr);
    k_scan3<<<ROWS/TT, DI>>>(xzp, xdbl, dt_proj_w, dt_proj_b, A_log, Dp,
        conv1d_w, conv1d_b, ygp);
    gemm_bf<128,1,true><<<dim3(1,256),256>>>(ygp, out_proj_w, nullptr, zsb,
        ROWS, CC, DI, 128, DI, CC, nullptr, nullptr, nullptr, nullptr);
    // 4) attention (qkv packed bf16, Q pre-scaled)
    gemm_bf<128,4,false><<<dim3(3,256),256>>>(zsb, attn_in_w, attn_in_b, qkvp,
        ROWS, 3*CC, CC, CC, CC, 192, nullptr, nullptr, nullptr, nullptr);
    k_flash2<<<dim3(4, NBATCH), 256, 56320>>>(qkvp, orpp);
    // 5) out = x_in, then attn_out + LayerNorm + coalesced scatter-add
    {
        int n4 = (BB*TT*CC*NSP)/4;
        k_copy<<<(n4+255)/256, 256>>>((const float4*)x_in, (float4*)out, n4);
    }
    gemm_bf<128,2,true><<<dim3(1,256),256>>>(orpp, attn_out_w, attn_out_b, out,
        ROWS, CC, CC, 64, CC, NSP, zsb, ln_w, ln_b, idx);
}